// round 10
// baseline (speedup 1.0000x reference)
#include <cuda_runtime.h>
#include <math.h>

// Problem constants
#define Bq 16
#define Dq 64
#define Sq 256
#define Hq 128
#define H3 384
#define NROW (Bq*Dq*Sq)   // 262144
#define BDq (Bq*Dq)       // 1024
#define NLOOP 10

// Scratch (device globals: allocation-free rule)
__device__ float g_node[NROW*Hq];
__device__ float g_tmp [NROW*Hq];
__device__ float g_agg [NROW*Hq];
__device__ float g_gi  [NROW*H3];
__device__ float g_gh  [NROW*H3];
__device__ float g_wiht[Hq*H3];
__device__ float g_whht[Hq*H3];

// ---------------------------------------------------------------------------
// XLA EmitFastTanh (f32): Eigen rational poly, clamp ±7.90531110763549805,
// |x|<0.0004 -> x, UNFUSED mul/add (best measured across R4..R9).
// ---------------------------------------------------------------------------
__device__ __forceinline__ float tanh_xla(float x){
    float ax = fabsf(x);
    if (ax < 0.0004f) return x;
    float xc = fminf(fmaxf(x, -7.90531110763549805f), 7.90531110763549805f);
    float a  = __fmul_rn(xc, xc);
    float p = __fadd_rn(__fmul_rn(a, -2.76076847742355e-16f), 2.00018790482477e-13f);
    p = __fadd_rn(__fmul_rn(a, p), -8.60467152213735e-11f);
    p = __fadd_rn(__fmul_rn(a, p),  5.12229709037114e-08f);
    p = __fadd_rn(__fmul_rn(a, p),  1.48572235717979e-05f);
    p = __fadd_rn(__fmul_rn(a, p),  6.37261928875436e-04f);
    p = __fadd_rn(__fmul_rn(a, p),  4.89352455891786e-03f);
    float num = __fmul_rn(xc, p);
    float q = __fadd_rn(__fmul_rn(a, 1.19825839466702e-06f), 1.18534705686654e-04f);
    q = __fadd_rn(__fmul_rn(a, q), 2.26843463243900e-03f);
    q = __fadd_rn(__fmul_rn(a, q), 4.89352518554385e-03f);
    return __fdiv_rn(num, q);
}

// ---------------------------------------------------------------------------
// Cephes/Eigen f32 exp (XLA CPU vectorized-exp style), UNFUSED mul/add:
// clamp, m = floor(x*log2e + 0.5), Cody-Waite 2-part ln2 reduction,
// degree-5 poly, scale by 2^m via exponent bits.
// ---------------------------------------------------------------------------
__device__ __forceinline__ float exp_cephes(float x){
    x = fminf(x,  88.3762626647950f);
    x = fmaxf(x, -88.3762626647949f);
    float m = floorf(__fadd_rn(__fmul_rn(x, 1.44269504088896341f), 0.5f));
    float r = __fsub_rn(x, __fmul_rn(m, 0.693359375f));
    r = __fsub_rn(r, __fmul_rn(m, -2.12194440e-4f));
    float z = __fmul_rn(r, r);
    float y = 1.9875691500e-4f;
    y = __fadd_rn(__fmul_rn(y, r), 1.3981999507e-3f);
    y = __fadd_rn(__fmul_rn(y, r), 8.3334519073e-3f);
    y = __fadd_rn(__fmul_rn(y, r), 4.1665795894e-2f);
    y = __fadd_rn(__fmul_rn(y, r), 1.6666665459e-1f);
    y = __fadd_rn(__fmul_rn(y, r), 5.0000001201e-1f);
    y = __fadd_rn(__fmul_rn(y, z), r);
    y = __fadd_rn(y, 1.0f);
    int mi = (int)m;
    float s = __int_as_float((mi + 127) << 23);
    return __fmul_rn(y, s);
}

// logistic(x) = 1 / (1 + exp(-x)) with Cephes exp, unfused.
__device__ __forceinline__ float sigmoid_xla(float x){
    float e = exp_cephes(-x);
    return __fdiv_rn(1.f, __fadd_rn(1.f, e));
}

// ---------------------------------------------------------------------------
// Embedding gather: node[n][:] = embed[idx[n]][:]
// ---------------------------------------------------------------------------
__global__ void k_gather(const int* __restrict__ idx,
                         const float* __restrict__ embed,
                         float* __restrict__ node)
{
    size_t t = (size_t)blockIdx.x*blockDim.x + threadIdx.x;   // NROW*32 threads
    size_t n = t >> 5; int c = (int)(t & 31) << 2;
    float4 v = *(const float4*)(embed + (size_t)idx[n]*Hq + c);
    *(float4*)(node + n*Hq + c) = v;
}

// ---------------------------------------------------------------------------
// Weight transpose: wt[k][j] = w[j][k], w is [H3][Hq]
// ---------------------------------------------------------------------------
__global__ void k_transpose(const float* __restrict__ w, float* __restrict__ wt)
{
    int t = blockIdx.x*blockDim.x + threadIdx.x;
    if (t < H3*Hq){ int j = t / Hq, k = t % Hq; wt[k*H3 + j] = w[t]; }
}

// ---------------------------------------------------------------------------
// GEMM: C[row][c] = sum_k A[row][k]*W[k*ldw+c] (+bias, opt tanh)
// Sequential-k FMA per output element (matches Eigen/cuBLAS fp32 chains).
// Block: 256 threads, 128x128 tile, thread tile 8x8.
// ---------------------------------------------------------------------------
__global__ __launch_bounds__(256, 1)
void k_gemm(const float* __restrict__ A,
            const float* __restrict__ W, int ldw,
            const float* __restrict__ bias,
            float* __restrict__ C, int ldc, int act)
{
    extern __shared__ float smem[];
    float* As = smem;              // 128*128  [k][r]
    float* Ws = smem + 128*128;    // 128*128  [k][c]

    const int tid = threadIdx.x;
    const size_t row0 = (size_t)blockIdx.x * 128;

    #pragma unroll
    for (int i = 0; i < 16; i++){
        int f  = tid + i*256;           // 0..4095
        int k  = f >> 5;
        int c4 = (f & 31) << 2;
        *(float4*)&Ws[k*128 + c4] = *(const float4*)(W + (size_t)k*ldw + c4);
    }
    #pragma unroll
    for (int i = 0; i < 16; i++){
        int f  = tid + i*256;
        int r  = f & 127;
        int k4 = (f >> 7) << 2;
        float4 v = *(const float4*)(A + (row0 + r)*Hq + k4);
        As[(k4+0)*128 + r] = v.x;
        As[(k4+1)*128 + r] = v.y;
        As[(k4+2)*128 + r] = v.z;
        As[(k4+3)*128 + r] = v.w;
    }
    __syncthreads();

    const int tx = tid & 15, ty = tid >> 4;
    const int cb = tx*8, rb = ty*8;

    float acc[8][8];
    #pragma unroll
    for (int i=0;i<8;i++)
        #pragma unroll
        for (int j=0;j<8;j++) acc[i][j] = 0.f;

    #pragma unroll 4
    for (int k = 0; k < 128; k++){
        float a[8], b[8];
        *(float4*)&a[0] = *(float4*)&As[k*128 + rb];
        *(float4*)&a[4] = *(float4*)&As[k*128 + rb + 4];
        *(float4*)&b[0] = *(float4*)&Ws[k*128 + cb];
        *(float4*)&b[4] = *(float4*)&Ws[k*128 + cb + 4];
        #pragma unroll
        for (int i=0;i<8;i++)
            #pragma unroll
            for (int j=0;j<8;j++)
                acc[i][j] = fmaf(a[i], b[j], acc[i][j]);
    }

    float bv[8];
    #pragma unroll
    for (int j=0;j<8;j++) bv[j] = bias ? bias[cb+j] : 0.f;

    #pragma unroll
    for (int i=0;i<8;i++){
        float* crow = C + (row0 + rb + i)*(size_t)ldc + cb;
        float o[8];
        #pragma unroll
        for (int j=0;j<8;j++){
            float v = __fadd_rn(acc[i][j], bv[j]);
            o[j] = act ? tanh_xla(v) : v;
        }
        *(float4*)(crow)   = make_float4(o[0],o[1],o[2],o[3]);
        *(float4*)(crow+4) = make_float4(o[4],o[5],o[6],o[7]);
    }
}

// ---------------------------------------------------------------------------
// Batched aggregation: per (b,d): C[256][128] = A[256][256] @ B[256][128]
// Sequential-k FMA (k = t ascending). Block = one (b,d), thread tile 8x16.
// ---------------------------------------------------------------------------
__global__ __launch_bounds__(256, 1)
void k_agg(const float* __restrict__ adj,
           const float* __restrict__ tmp,
           float* __restrict__ agg)
{
    extern __shared__ float smem[];
    float* Bs  = smem;             // 256*128   [t][h]
    float* Ast = smem + 256*128;   // 16*256    [kk][s]

    const int bd = blockIdx.x;
    const float* A  = adj + (size_t)bd*Sq*Sq;
    const float* Bm = tmp + (size_t)bd*Sq*Hq;
    float*       Cm = agg + (size_t)bd*Sq*Hq;
    const int tid = threadIdx.x;

    #pragma unroll
    for (int i = 0; i < 32; i++){
        int f = tid + i*256;  // 0..8191 float4s
        ((float4*)Bs)[f] = ((const float4*)Bm)[f];
    }

    const int hx = tid & 7, sy = tid >> 3;
    const int hb = hx*16, sb = sy*8;

    float acc[8][16];
    #pragma unroll
    for (int i=0;i<8;i++)
        #pragma unroll
        for (int j=0;j<16;j++) acc[i][j] = 0.f;

    for (int k0 = 0; k0 < 256; k0 += 16){
        __syncthreads();
        {
            const float4* src = (const float4*)(A + (size_t)tid*Sq + k0);
            #pragma unroll
            for (int q=0;q<4;q++){
                float4 v = src[q];
                Ast[(q*4+0)*256 + tid] = v.x;
                Ast[(q*4+1)*256 + tid] = v.y;
                Ast[(q*4+2)*256 + tid] = v.z;
                Ast[(q*4+3)*256 + tid] = v.w;
            }
        }
        __syncthreads();
        #pragma unroll
        for (int kk = 0; kk < 16; kk++){
            const int k = k0 + kk;
            float a[8], b[16];
            *(float4*)&a[0]  = *(float4*)&Ast[kk*256 + sb];
            *(float4*)&a[4]  = *(float4*)&Ast[kk*256 + sb + 4];
            *(float4*)&b[0]  = *(float4*)&Bs[k*128 + hb];
            *(float4*)&b[4]  = *(float4*)&Bs[k*128 + hb + 4];
            *(float4*)&b[8]  = *(float4*)&Bs[k*128 + hb + 8];
            *(float4*)&b[12] = *(float4*)&Bs[k*128 + hb + 12];
            #pragma unroll
            for (int i=0;i<8;i++)
                #pragma unroll
                for (int j=0;j<16;j++)
                    acc[i][j] = fmaf(a[i], b[j], acc[i][j]);
        }
    }

    #pragma unroll
    for (int i=0;i<8;i++){
        float* crow = Cm + (size_t)(sb + i)*Hq + hb;
        #pragma unroll
        for (int q=0;q<4;q++)
            *(float4*)(crow + q*4) =
                make_float4(acc[i][q*4+0],acc[i][q*4+1],acc[i][q*4+2],acc[i][q*4+3]);
    }
}

// ---------------------------------------------------------------------------
// GRU elementwise combine — all ops UNFUSED; poly tanh + Cephes-exp sigmoid.
// ---------------------------------------------------------------------------
__device__ __forceinline__ float gru1(float ir,float iz,float inn,
                                      float hr,float hz,float hn,float h){
    float r  = sigmoid_xla(__fadd_rn(ir, hr));
    float z  = sigmoid_xla(__fadd_rn(iz, hz));
    float rhn = __fmul_rn(r, hn);
    float ng  = tanh_xla(__fadd_rn(inn, rhn));
    float omz = __fsub_rn(1.f, z);
    float t0  = __fmul_rn(omz, ng);
    float t1  = __fmul_rn(z, h);
    return __fadd_rn(t0, t1);
}

__global__ void k_gru(const float* __restrict__ gi,
                      const float* __restrict__ gh,
                      float* __restrict__ node)
{
    size_t t = (size_t)blockIdx.x*blockDim.x + threadIdx.x;  // NROW*32
    size_t n = t >> 5; int c = (int)(t & 31) << 2;
    const float* gin = gi + n*H3 + c;
    const float* ghn = gh + n*H3 + c;
    float* hp = node + n*Hq + c;
    float4 ir  = *(const float4*)(gin);
    float4 iz  = *(const float4*)(gin + 128);
    float4 inn = *(const float4*)(gin + 256);
    float4 hr  = *(const float4*)(ghn);
    float4 hz  = *(const float4*)(ghn + 128);
    float4 hn  = *(const float4*)(ghn + 256);
    float4 h   = *(float4*)hp;
    float4 o;
    o.x = gru1(ir.x,iz.x,inn.x,hr.x,hz.x,hn.x,h.x);
    o.y = gru1(ir.y,iz.y,inn.y,hr.y,hz.y,hn.y,h.y);
    o.z = gru1(ir.z,iz.z,inn.z,hr.z,hz.z,hn.z,h.z);
    o.w = gru1(ir.w,iz.w,inn.w,hr.w,hz.w,hn.w,h.w);
    *(float4*)hp = o;
}

// ---------------------------------------------------------------------------
// Final: out[n] = tanh(dot(t2[n], w3) + b3), one warp per row
// ---------------------------------------------------------------------------
__global__ void k_final(const float* __restrict__ t2,
                        const float* __restrict__ w3,
                        const float* __restrict__ b3,
                        float* __restrict__ out)
{
    size_t row = ((size_t)blockIdx.x*blockDim.x + threadIdx.x) >> 5;
    int lane = threadIdx.x & 31;
    const float* a = t2 + row*Hq + lane*4;
    const float* w = w3 + lane*4;
    float p = 0.f;
    #pragma unroll
    for (int q=0;q<4;q++) p = fmaf(a[q], w[q], p);
    #pragma unroll
    for (int o = 16; o; o >>= 1) p = __fadd_rn(p, __shfl_xor_sync(0xFFFFFFFFu, p, o));
    if (lane == 0) out[row] = tanh_xla(__fadd_rn(p, b3[0]));
}

// ---------------------------------------------------------------------------
extern "C" void kernel_launch(void* const* d_in, const int* in_sizes, int n_in,
                              void* d_out, int out_size)
{
    const int*   input_var = (const int*)  d_in[0];
    const float* adjacency = (const float*)d_in[1];
    const float* embed     = (const float*)d_in[2];
    const float* gnn_w     = (const float*)d_in[3];
    const float* gnn_b     = (const float*)d_in[4];
    const float* w_ih      = (const float*)d_in[5];
    const float* w_hh      = (const float*)d_in[6];
    const float* b_ih      = (const float*)d_in[7];
    const float* b_hh      = (const float*)d_in[8];
    const float* mlp_w1    = (const float*)d_in[9];
    const float* mlp_b1    = (const float*)d_in[10];
    const float* mlp_w2    = (const float*)d_in[11];
    const float* mlp_b2    = (const float*)d_in[12];
    const float* mlp_w3    = (const float*)d_in[13];
    const float* mlp_b3    = (const float*)d_in[14];
    float* out = (float*)d_out;

    float *node,*tmp,*agg,*gi,*gh,*wiht,*whht;
    cudaGetSymbolAddress((void**)&node, g_node);
    cudaGetSymbolAddress((void**)&tmp,  g_tmp);
    cudaGetSymbolAddress((void**)&agg,  g_agg);
    cudaGetSymbolAddress((void**)&gi,   g_gi);
    cudaGetSymbolAddress((void**)&gh,   g_gh);
    cudaGetSymbolAddress((void**)&wiht, g_wiht);
    cudaGetSymbolAddress((void**)&whht, g_whht);

    const int GEMM_SMEM = 128*128*2*sizeof(float);          // 131072
    const int AGG_SMEM  = (256*128 + 16*256)*sizeof(float); // 147456
    cudaFuncSetAttribute(k_gemm, cudaFuncAttributeMaxDynamicSharedMemorySize, GEMM_SMEM);
    cudaFuncSetAttribute(k_agg,  cudaFuncAttributeMaxDynamicSharedMemorySize, AGG_SMEM);

    k_transpose<<<(H3*Hq + 255)/256, 256>>>(w_ih, wiht);
    k_transpose<<<(H3*Hq + 255)/256, 256>>>(w_hh, whht);
    k_gather<<<NROW*32/256, 256>>>(input_var, embed, node);

    for (int it = 0; it < NLOOP; it++){
        // tmp = node @ gnn_w + gnn_b
        k_gemm<<<NROW/128, 256, GEMM_SMEM>>>(node, gnn_w, 128, gnn_b, tmp, 128, 0);
        // agg[b,d] = adjacency[b,d] @ tmp[b,d]
        k_agg<<<BDq, 256, AGG_SMEM>>>(adjacency, tmp, agg);
        // gi = agg @ w_ih^T + b_ih ; gh = node @ w_hh^T + b_hh   (3 column chunks)
        for (int c = 0; c < 3; c++){
            k_gemm<<<NROW/128, 256, GEMM_SMEM>>>(agg,  wiht + c*128, H3, b_ih + c*128, gi + c*128, H3, 0);
            k_gemm<<<NROW/128, 256, GEMM_SMEM>>>(node, whht + c*128, H3, b_hh + c*128, gh + c*128, H3, 0);
        }
        k_gru<<<NROW*32/256, 256>>>(gi, gh, node);
    }

    // MLP head
    k_gemm<<<NROW/128, 256, GEMM_SMEM>>>(node, mlp_w1, 128, mlp_b1, tmp, 128, 1);
    k_gemm<<<NROW/128, 256, GEMM_SMEM>>>(tmp,  mlp_w2, 128, mlp_b2, agg, 128, 1);
    k_final<<<NROW/8, 256>>>(agg, mlp_w3, mlp_b3, out);
}